// round 2
// baseline (speedup 1.0000x reference)
#include <cuda_runtime.h>
#include <cstdint>

#define N_NODES 40000
#define N_EDGES 640000
#define D 128
#define BN_EPS 1e-5f

// ---------------- device scratch (no allocations allowed) ----------------
__device__ float g_agg[(size_t)N_NODES * D];   // segment sums
__device__ float g_deg[N_NODES];               // degrees
__device__ float g_invdeg[N_NODES];            // 1/max(deg,1)
__device__ float g_y[(size_t)N_NODES * D];     // pre-batchnorm activations
__device__ float g_colsum[D];
__device__ float g_colsq[D];
__device__ float g_scale[D];
__device__ float g_shift[D];

// ---------------- K1: zero scratch ----------------
__global__ void k_zero() {
    int i = blockIdx.x * blockDim.x + threadIdx.x;
    int total4 = N_NODES * D / 4;
    if (i < total4) {
        ((float4*)g_agg)[i] = make_float4(0.f, 0.f, 0.f, 0.f);
    }
    if (i < N_NODES) g_deg[i] = 0.f;
    if (i < D) { g_colsum[i] = 0.f; g_colsq[i] = 0.f; }
}

// ---------------- K2: edge scatter (warp per edge) ----------------
__global__ void __launch_bounds__(256) k_scatter(const float* __restrict__ h,
                                                 const int* __restrict__ src,
                                                 const int* __restrict__ dst) {
    int gtid = blockIdx.x * blockDim.x + threadIdx.x;
    int e = gtid >> 5;            // edge index
    int lane = gtid & 31;         // 32 lanes x float4 = 128 floats
    if (e >= N_EDGES) return;
    int s = src[e];
    int d = dst[e];
    float4 v = ((const float4*)(h))[(size_t)s * (D / 4) + lane];
    float* p = g_agg + (size_t)d * D + lane * 4;
    asm volatile("red.global.add.v4.f32 [%0], {%1,%2,%3,%4};"
                 :: "l"(p), "f"(v.x), "f"(v.y), "f"(v.z), "f"(v.w)
                 : "memory");
    if (lane == 0) atomicAdd(&g_deg[d], 1.0f);
}

// ---------------- K3: inverse degree ----------------
__global__ void k_invdeg() {
    int i = blockIdx.x * blockDim.x + threadIdx.x;
    if (i < N_NODES) g_invdeg[i] = 1.0f / fmaxf(g_deg[i], 1.0f);
}

// ---------------- K4: fused dual GEMM + bias + relu + snorm + col stats ----
// out_pre = relu(h@Ws + (agg*invdeg)@Wn + b) * snorm   -> g_y
// also accumulates per-column sum / sumsq into g_colsum/g_colsq.
// BM=64 rows per block, BN=128 (all cols), K=256 (h ++ hneigh), BK=16.
// 256 threads, each computes an 8x4 microtile.
#define BM 64
#define BK 16
__global__ void __launch_bounds__(256) k_gemm(const float* __restrict__ h,
                                              const float* __restrict__ Ws,
                                              const float* __restrict__ Wn,
                                              const float* __restrict__ bias,
                                              const float* __restrict__ snorm) {
    __shared__ float As[BK][BM];       // [k][row]
    __shared__ float Bs[BK][D];        // [k][col]
    __shared__ float red[8][D];        // epilogue reduction buffer

    const int tid = threadIdx.x;
    const int cx  = tid & 31;          // col group: cols cx*4 .. cx*4+3
    const int ry  = tid >> 5;          // row group: rows ry*8 .. ry*8+7
    const int row0 = blockIdx.x * BM;

    // A-tile loader mapping: each thread loads one float4 along k
    const int lrow = tid >> 2;         // 0..63
    const int kq   = tid & 3;          // 0..3  (k quad within BK)
    const int grow = row0 + lrow;
    const float invd = g_invdeg[grow];

    float acc[8][4];
    #pragma unroll
    for (int j = 0; j < 8; j++)
        #pragma unroll
        for (int c = 0; c < 4; c++) acc[j][c] = 0.f;

    for (int kc = 0; kc < 2 * D; kc += BK) {
        // ---- load A tile (transposed into [k][row]) ----
        int kg = kc + kq * 4;
        float4 a4;
        if (kg < D) {
            a4 = *(const float4*)(h + (size_t)grow * D + kg);
        } else {
            a4 = *(const float4*)(g_agg + (size_t)grow * D + (kg - D));
            a4.x *= invd; a4.y *= invd; a4.z *= invd; a4.w *= invd;
        }
        As[kq * 4 + 0][lrow] = a4.x;
        As[kq * 4 + 1][lrow] = a4.y;
        As[kq * 4 + 2][lrow] = a4.z;
        As[kq * 4 + 3][lrow] = a4.w;

        // ---- load B tile ----
        #pragma unroll
        for (int i = 0; i < 2; i++) {
            int li = tid + i * 256;
            int kk = li >> 5;
            int n4 = li & 31;
            int kgb = kc + kk;
            const float* Wp = (kgb < D) ? (Ws + (size_t)kgb * D)
                                        : (Wn + (size_t)(kgb - D) * D);
            *(float4*)&Bs[kk][n4 * 4] = *(const float4*)(Wp + n4 * 4);
        }
        __syncthreads();

        // ---- compute ----
        #pragma unroll
        for (int k = 0; k < BK; k++) {
            float4 b4 = *(float4*)&Bs[k][cx * 4];
            float4 a0 = *(float4*)&As[k][ry * 8];
            float4 a1 = *(float4*)&As[k][ry * 8 + 4];
            float a[8] = {a0.x, a0.y, a0.z, a0.w, a1.x, a1.y, a1.z, a1.w};
            #pragma unroll
            for (int j = 0; j < 8; j++) {
                acc[j][0] += a[j] * b4.x;
                acc[j][1] += a[j] * b4.y;
                acc[j][2] += a[j] * b4.z;
                acc[j][3] += a[j] * b4.w;
            }
        }
        __syncthreads();
    }

    // ---- epilogue: bias + relu + snorm, write y, accumulate col stats ----
    float4 bb = *(const float4*)(bias + cx * 4);
    float lsum[4] = {0.f, 0.f, 0.f, 0.f};
    float lsq[4]  = {0.f, 0.f, 0.f, 0.f};
    #pragma unroll
    for (int j = 0; j < 8; j++) {
        int r = row0 + ry * 8 + j;
        float sn = snorm[r];
        float4 v;
        v.x = fmaxf(acc[j][0] + bb.x, 0.f) * sn;
        v.y = fmaxf(acc[j][1] + bb.y, 0.f) * sn;
        v.z = fmaxf(acc[j][2] + bb.z, 0.f) * sn;
        v.w = fmaxf(acc[j][3] + bb.w, 0.f) * sn;
        *(float4*)(g_y + (size_t)r * D + cx * 4) = v;
        lsum[0] += v.x; lsum[1] += v.y; lsum[2] += v.z; lsum[3] += v.w;
        lsq[0] += v.x * v.x; lsq[1] += v.y * v.y;
        lsq[2] += v.z * v.z; lsq[3] += v.w * v.w;
    }

    *(float4*)&red[ry][cx * 4] = make_float4(lsum[0], lsum[1], lsum[2], lsum[3]);
    __syncthreads();
    if (tid < D) {
        float s = 0.f;
        #pragma unroll
        for (int r = 0; r < 8; r++) s += red[r][tid];
        atomicAdd(&g_colsum[tid], s);
    }
    __syncthreads();
    *(float4*)&red[ry][cx * 4] = make_float4(lsq[0], lsq[1], lsq[2], lsq[3]);
    __syncthreads();
    if (tid < D) {
        float s = 0.f;
        #pragma unroll
        for (int r = 0; r < 8; r++) s += red[r][tid];
        atomicAdd(&g_colsq[tid], s);
    }
}

// ---------------- K5: batchnorm finalize (fold into scale/shift) ----------
__global__ void k_bn(const float* __restrict__ gamma, const float* __restrict__ beta) {
    int c = threadIdx.x;
    if (c >= D) return;
    float m  = g_colsum[c] * (1.0f / N_NODES);
    float v  = g_colsq[c] * (1.0f / N_NODES) - m * m;
    float rs = rsqrtf(v + BN_EPS);
    float sc = rs * gamma[c];
    g_scale[c] = sc;
    g_shift[c] = beta[c] - m * sc;
}

// ---------------- K6: out = h + y*scale + shift ----------------
__global__ void __launch_bounds__(256) k_final(const float* __restrict__ h,
                                               float* __restrict__ out) {
    int i = blockIdx.x * blockDim.x + threadIdx.x;
    if (i >= N_NODES * (D / 4)) return;
    int c4 = i & (D / 4 - 1);
    float4 y  = ((const float4*)g_y)[i];
    float4 hh = ((const float4*)h)[i];
    float4 sc = *(const float4*)&g_scale[c4 * 4];
    float4 sh = *(const float4*)&g_shift[c4 * 4];
    float4 o;
    o.x = hh.x + y.x * sc.x + sh.x;
    o.y = hh.y + y.y * sc.y + sh.y;
    o.z = hh.z + y.z * sc.z + sh.z;
    o.w = hh.w + y.w * sc.w + sh.w;
    ((float4*)out)[i] = o;
}

// ---------------- launch ----------------
extern "C" void kernel_launch(void* const* d_in, const int* in_sizes, int n_in,
                              void* d_out, int out_size) {
    const float* h      = (const float*)d_in[0];
    const float* snorm  = (const float*)d_in[1];
    const float* Ws     = (const float*)d_in[2];
    const float* Wn     = (const float*)d_in[3];
    const float* bias   = (const float*)d_in[4];
    const float* gamma  = (const float*)d_in[5];
    const float* beta   = (const float*)d_in[6];
    const int*   src    = (const int*)d_in[7];
    const int*   dst    = (const int*)d_in[8];
    float* out = (float*)d_out;

    int zero_blocks = (N_NODES * D / 4 + 255) / 256;
    k_zero<<<zero_blocks, 256>>>();

    int scatter_blocks = (N_EDGES * 32) / 256;       // warp per edge
    k_scatter<<<scatter_blocks, 256>>>(h, src, dst);

    k_invdeg<<<(N_NODES + 255) / 256, 256>>>();

    k_gemm<<<N_NODES / BM, 256>>>(h, Ws, Wn, bias, snorm);

    k_bn<<<1, D>>>(gamma, beta);

    k_final<<<(N_NODES * (D / 4) + 255) / 256, 256>>>(h, out);
}

// round 3
// speedup vs baseline: 1.2743x; 1.2743x over previous
#include <cuda_runtime.h>
#include <cuda_fp16.h>
#include <cstdint>

#define N_NODES 40000
#define N_EDGES 640000
#define D 128
#define BN_EPS 1e-5f
#define SCAN_BLOCKS ((N_NODES + 255) / 256)   // 157

// ---------------- device scratch (no allocations allowed) ----------------
__device__ __half g_h16[(size_t)N_NODES * D];     // f16 copy of h
__device__ float  g_hneigh[(size_t)N_NODES * D];  // mean-aggregated neighbors (fp32)
__device__ float  g_y[(size_t)N_NODES * D];       // pre-batchnorm activations
__device__ int    g_cnt[N_NODES];                 // in-degree
__device__ int    g_rowstart[N_NODES];            // CSR row offsets (exclusive)
__device__ int    g_fill[N_NODES];                // fill cursors
__device__ int    g_bsum[SCAN_BLOCKS];            // scan block sums
__device__ int    g_csr[N_EDGES];                 // src ids grouped by dst
__device__ float  g_colsum[D];
__device__ float  g_colsq[D];
__device__ float  g_scale[D];
__device__ float  g_shift[D];

// ---------------- K1: h -> f16, zero counters/stats ----------------
__global__ void __launch_bounds__(256) k_h16(const float* __restrict__ h) {
    int i = blockIdx.x * blockDim.x + threadIdx.x;   // over float4 chunks
    if (i < N_NODES * (D / 4)) {
        float4 v = ((const float4*)h)[i];
        __half2 lo = __floats2half2_rn(v.x, v.y);
        __half2 hi = __floats2half2_rn(v.z, v.w);
        uint2 u;
        u.x = *(unsigned*)&lo;
        u.y = *(unsigned*)&hi;
        ((uint2*)g_h16)[i] = u;
    }
    if (i < N_NODES) g_cnt[i] = 0;
    if (i < D) { g_colsum[i] = 0.f; g_colsq[i] = 0.f; }
}

// ---------------- K2: degree histogram ----------------
__global__ void __launch_bounds__(256) k_hist(const int* __restrict__ dst) {
    int e = blockIdx.x * blockDim.x + threadIdx.x;
    if (e < N_EDGES) atomicAdd(&g_cnt[dst[e]], 1);
}

// ---------------- K3a: per-block exclusive scan ----------------
__global__ void __launch_bounds__(256) k_scan1() {
    __shared__ int sh[256];
    int i = blockIdx.x * 256 + threadIdx.x;
    int v = (i < N_NODES) ? g_cnt[i] : 0;
    sh[threadIdx.x] = v;
    __syncthreads();
    #pragma unroll
    for (int off = 1; off < 256; off <<= 1) {
        int t = (threadIdx.x >= off) ? sh[threadIdx.x - off] : 0;
        __syncthreads();
        sh[threadIdx.x] += t;
        __syncthreads();
    }
    if (i < N_NODES) g_rowstart[i] = sh[threadIdx.x] - v;   // exclusive within block
    if (threadIdx.x == 255) g_bsum[blockIdx.x] = sh[255];
}

// ---------------- K3b: scan of block sums (single block) ----------------
__global__ void __launch_bounds__(256) k_scan2() {
    __shared__ int sh[256];
    int tid = threadIdx.x;
    int v = (tid < SCAN_BLOCKS) ? g_bsum[tid] : 0;
    sh[tid] = v;
    __syncthreads();
    #pragma unroll
    for (int off = 1; off < 256; off <<= 1) {
        int t = (tid >= off) ? sh[tid - off] : 0;
        __syncthreads();
        sh[tid] += t;
        __syncthreads();
    }
    if (tid < SCAN_BLOCKS) g_bsum[tid] = sh[tid] - v;       // exclusive
}

// ---------------- K3c: add block offsets, init fill cursors ----------------
__global__ void __launch_bounds__(256) k_scan3() {
    int i = blockIdx.x * 256 + threadIdx.x;
    if (i < N_NODES) {
        int rs = g_rowstart[i] + g_bsum[i >> 8];
        g_rowstart[i] = rs;
        g_fill[i] = rs;
    }
}

// ---------------- K4: fill CSR ----------------
__global__ void __launch_bounds__(256) k_fill(const int* __restrict__ src,
                                              const int* __restrict__ dst) {
    int e = blockIdx.x * blockDim.x + threadIdx.x;
    if (e < N_EDGES) {
        int d = dst[e];
        int pos = atomicAdd(&g_fill[d], 1);
        g_csr[pos] = src[e];
    }
}

// ---------------- K5: warp-per-node gather (f16 messages, fp32 accum) -----
__global__ void __launch_bounds__(256) k_gather() {
    int w = (blockIdx.x * 256 + threadIdx.x) >> 5;
    int lane = threadIdx.x & 31;
    if (w >= N_NODES) return;
    int rs  = g_rowstart[w];
    int deg = g_cnt[w];
    const uint2* hp = (const uint2*)g_h16;   // one row = 32 uint2 (4 halves each)

    float4 acc = make_float4(0.f, 0.f, 0.f, 0.f);
    int j = 0;
    for (; j + 2 <= deg; j += 2) {
        int s0 = g_csr[rs + j];
        int s1 = g_csr[rs + j + 1];
        uint2 u0 = hp[(size_t)s0 * 32 + lane];
        uint2 u1 = hp[(size_t)s1 * 32 + lane];
        float2 a0 = __half22float2(*(__half2*)&u0.x);
        float2 a1 = __half22float2(*(__half2*)&u0.y);
        float2 b0 = __half22float2(*(__half2*)&u1.x);
        float2 b1 = __half22float2(*(__half2*)&u1.y);
        acc.x += a0.x + b0.x;  acc.y += a0.y + b0.y;
        acc.z += a1.x + b1.x;  acc.w += a1.y + b1.y;
    }
    if (j < deg) {
        int s0 = g_csr[rs + j];
        uint2 u0 = hp[(size_t)s0 * 32 + lane];
        float2 a0 = __half22float2(*(__half2*)&u0.x);
        float2 a1 = __half22float2(*(__half2*)&u0.y);
        acc.x += a0.x;  acc.y += a0.y;
        acc.z += a1.x;  acc.w += a1.y;
    }
    float inv = 1.0f / fmaxf((float)deg, 1.0f);
    float4 o;
    o.x = acc.x * inv; o.y = acc.y * inv; o.z = acc.z * inv; o.w = acc.w * inv;
    *(float4*)(g_hneigh + (size_t)w * D + lane * 4) = o;
}

// ---------------- K6: fused dual GEMM (packed f32x2) + epilogue -----------
// y = relu([h | hneigh] @ [Ws; Wn] + b) * snorm ; col stats accumulated.
#define BM 64
#define BK 16
__global__ void __launch_bounds__(256) k_gemm(const float* __restrict__ h,
                                              const float* __restrict__ Ws,
                                              const float* __restrict__ Wn,
                                              const float* __restrict__ bias,
                                              const float* __restrict__ snorm) {
    __shared__ __align__(16) float As[BK][BM];   // [k][row]
    __shared__ __align__(16) float Bs[BK][D];    // [k][col]
    __shared__ float red[8][D];

    const int tid = threadIdx.x;
    const int cx  = tid & 31;          // cols cx*4 .. cx*4+3
    const int ry  = tid >> 5;          // rows ry*8 .. ry*8+7
    const int row0 = blockIdx.x * BM;

    const int lrow = tid >> 2;         // 0..63 (A loader row)
    const int kq   = tid & 3;          // k-quad within BK
    const int grow = row0 + lrow;

    // packed accumulators: [row-pair 0..3][col 0..3], pair = rows (2rp, 2rp+1)
    unsigned long long acc[4][4];
    #pragma unroll
    for (int i = 0; i < 4; i++)
        #pragma unroll
        for (int c = 0; c < 4; c++) acc[i][c] = 0ull;

    for (int kc = 0; kc < 2 * D; kc += BK) {
        // ---- A tile (transposed into [k][row]) ----
        int kg = kc + kq * 4;
        const float* Ap = (kg < D) ? (h + (size_t)grow * D + kg)
                                   : (g_hneigh + (size_t)grow * D + (kg - D));
        float4 a4 = *(const float4*)Ap;
        As[kq * 4 + 0][lrow] = a4.x;
        As[kq * 4 + 1][lrow] = a4.y;
        As[kq * 4 + 2][lrow] = a4.z;
        As[kq * 4 + 3][lrow] = a4.w;

        // ---- B tile ----
        #pragma unroll
        for (int i = 0; i < 2; i++) {
            int li = tid + i * 256;
            int kk = li >> 5;
            int n4 = li & 31;
            int kgb = kc + kk;
            const float* Wp = (kgb < D) ? (Ws + (size_t)kgb * D)
                                        : (Wn + (size_t)(kgb - D) * D);
            *(float4*)&Bs[kk][n4 * 4] = *(const float4*)(Wp + n4 * 4);
        }
        __syncthreads();

        // ---- compute: 16 fma.f32x2 per k ----
        #pragma unroll
        for (int k = 0; k < BK; k++) {
            float4 b4 = *(float4*)&Bs[k][cx * 4];
            unsigned long long bp0, bp1, bp2, bp3;
            asm("mov.b64 %0,{%1,%2};" : "=l"(bp0) : "f"(b4.x), "f"(b4.x));
            asm("mov.b64 %0,{%1,%2};" : "=l"(bp1) : "f"(b4.y), "f"(b4.y));
            asm("mov.b64 %0,{%1,%2};" : "=l"(bp2) : "f"(b4.z), "f"(b4.z));
            asm("mov.b64 %0,{%1,%2};" : "=l"(bp3) : "f"(b4.w), "f"(b4.w));

            const ulonglong2* ap = (const ulonglong2*)&As[k][ry * 8];
            ulonglong2 a01 = ap[0];   // row pairs (0,1) (2,3)
            ulonglong2 a23 = ap[1];   // row pairs (4,5) (6,7)
            unsigned long long ar[4] = {a01.x, a01.y, a23.x, a23.y};

            #pragma unroll
            for (int rp = 0; rp < 4; rp++) {
                asm("fma.rn.f32x2 %0,%1,%2,%0;" : "+l"(acc[rp][0]) : "l"(ar[rp]), "l"(bp0));
                asm("fma.rn.f32x2 %0,%1,%2,%0;" : "+l"(acc[rp][1]) : "l"(ar[rp]), "l"(bp1));
                asm("fma.rn.f32x2 %0,%1,%2,%0;" : "+l"(acc[rp][2]) : "l"(ar[rp]), "l"(bp2));
                asm("fma.rn.f32x2 %0,%1,%2,%0;" : "+l"(acc[rp][3]) : "l"(ar[rp]), "l"(bp3));
            }
        }
        __syncthreads();
    }

    // ---- unpack to v[8][4] ----
    float v[8][4];
    #pragma unroll
    for (int rp = 0; rp < 4; rp++)
        #pragma unroll
        for (int c = 0; c < 4; c++) {
            float lo, hi;
            asm("mov.b64 {%0,%1},%2;" : "=f"(lo), "=f"(hi) : "l"(acc[rp][c]));
            v[2 * rp][c]     = lo;
            v[2 * rp + 1][c] = hi;
        }

    // ---- epilogue: bias + relu + snorm, write y, col stats ----
    float4 bb = *(const float4*)(bias + cx * 4);
    float lsum[4] = {0.f, 0.f, 0.f, 0.f};
    float lsq[4]  = {0.f, 0.f, 0.f, 0.f};
    #pragma unroll
    for (int j = 0; j < 8; j++) {
        int r = row0 + ry * 8 + j;
        float sn = snorm[r];
        float4 o;
        o.x = fmaxf(v[j][0] + bb.x, 0.f) * sn;
        o.y = fmaxf(v[j][1] + bb.y, 0.f) * sn;
        o.z = fmaxf(v[j][2] + bb.z, 0.f) * sn;
        o.w = fmaxf(v[j][3] + bb.w, 0.f) * sn;
        *(float4*)(g_y + (size_t)r * D + cx * 4) = o;
        lsum[0] += o.x; lsum[1] += o.y; lsum[2] += o.z; lsum[3] += o.w;
        lsq[0] += o.x * o.x; lsq[1] += o.y * o.y;
        lsq[2] += o.z * o.z; lsq[3] += o.w * o.w;
    }

    *(float4*)&red[ry][cx * 4] = make_float4(lsum[0], lsum[1], lsum[2], lsum[3]);
    __syncthreads();
    if (tid < D) {
        float s = 0.f;
        #pragma unroll
        for (int r = 0; r < 8; r++) s += red[r][tid];
        atomicAdd(&g_colsum[tid], s);
    }
    __syncthreads();
    *(float4*)&red[ry][cx * 4] = make_float4(lsq[0], lsq[1], lsq[2], lsq[3]);
    __syncthreads();
    if (tid < D) {
        float s = 0.f;
        #pragma unroll
        for (int r = 0; r < 8; r++) s += red[r][tid];
        atomicAdd(&g_colsq[tid], s);
    }
}

// ---------------- K7: batchnorm finalize ----------------
__global__ void k_bn(const float* __restrict__ gamma, const float* __restrict__ beta) {
    int c = threadIdx.x;
    if (c >= D) return;
    float m  = g_colsum[c] * (1.0f / N_NODES);
    float va = g_colsq[c] * (1.0f / N_NODES) - m * m;
    float rs = rsqrtf(va + BN_EPS);
    float sc = rs * gamma[c];
    g_scale[c] = sc;
    g_shift[c] = beta[c] - m * sc;
}

// ---------------- K8: out = h + y*scale + shift ----------------
__global__ void __launch_bounds__(256) k_final(const float* __restrict__ h,
                                               float* __restrict__ out) {
    int i = blockIdx.x * blockDim.x + threadIdx.x;
    if (i >= N_NODES * (D / 4)) return;
    int c4 = i & (D / 4 - 1);
    float4 y  = ((const float4*)g_y)[i];
    float4 hh = ((const float4*)h)[i];
    float4 sc = *(const float4*)&g_scale[c4 * 4];
    float4 sh = *(const float4*)&g_shift[c4 * 4];
    float4 o;
    o.x = hh.x + y.x * sc.x + sh.x;
    o.y = hh.y + y.y * sc.y + sh.y;
    o.z = hh.z + y.z * sc.z + sh.z;
    o.w = hh.w + y.w * sc.w + sh.w;
    ((float4*)out)[i] = o;
}

// ---------------- launch ----------------
extern "C" void kernel_launch(void* const* d_in, const int* in_sizes, int n_in,
                              void* d_out, int out_size) {
    const float* h      = (const float*)d_in[0];
    const float* snorm  = (const float*)d_in[1];
    const float* Ws     = (const float*)d_in[2];
    const float* Wn     = (const float*)d_in[3];
    const float* bias   = (const float*)d_in[4];
    const float* gamma  = (const float*)d_in[5];
    const float* beta   = (const float*)d_in[6];
    const int*   src    = (const int*)d_in[7];
    const int*   dst    = (const int*)d_in[8];
    float* out = (float*)d_out;

    int nd4_blocks = (N_NODES * (D / 4) + 255) / 256;
    int edge_blocks = (N_EDGES + 255) / 256;

    k_h16<<<nd4_blocks, 256>>>(h);
    k_hist<<<edge_blocks, 256>>>(dst);
    k_scan1<<<SCAN_BLOCKS, 256>>>();
    k_scan2<<<1, 256>>>();
    k_scan3<<<SCAN_BLOCKS, 256>>>();
    k_fill<<<edge_blocks, 256>>>(src, dst);
    k_gather<<<(N_NODES * 32 + 255) / 256, 256>>>();
    k_gemm<<<N_NODES / BM, 256>>>(h, Ws, Wn, bias, snorm);
    k_bn<<<1, D>>>(gamma, beta);
    k_final<<<nd4_blocks, 256>>>(h, out);
}